// round 1
// baseline (speedup 1.0000x reference)
#include <cuda_runtime.h>
#include <math.h>

// Problem constants (fixed by the reference)
#define B_IMGS 32
#define CIN    512
#define H_DIM  38
#define W_DIM  38
#define HW     1444          // 38*38
#define NA     3
#define NC     80
#define NOUT   255           // NA*(NC+5)
#define STRIDE_F 16.0f

// GEMM tiling
#define BM 128
#define BN 64
#define BK 16
#define TM 8
#define TN 4
#define NTHREADS 256

__constant__ float c_anchors[NA][2] = {{30.0f, 61.0f}, {62.0f, 45.0f}, {59.0f, 119.0f}};

__global__ __launch_bounds__(NTHREADS)
void yolo_fused_kernel(const float* __restrict__ xin,     // [B, CIN, HW]
                       const float* __restrict__ wmat,    // [NOUT, CIN]
                       const float* __restrict__ bias,    // [NOUT]
                       float* __restrict__ out)           // [B, HW, NOUT]
{
    const int nb = blockIdx.x;   // 0..3   (N tile)
    const int mb = blockIdx.y;   // 0..11  (HW tile)
    const int b  = blockIdx.z;   // 0..31  (image)

    const int hw0 = mb * BM;
    const int n0  = nb * BN;

    __shared__ float As[BK][BM];        // row stride 128 -> float4-aligned
    __shared__ float Bs[BK][BN + 4];    // pad 4 keeps float4 alignment

    const int tid = threadIdx.x;
    const int ty  = tid >> 4;    // 0..15 : row group (TM rows each)
    const int tx  = tid & 15;    // 0..15 : col group (TN cols each)

    float acc[TM][TN];
    #pragma unroll
    for (int i = 0; i < TM; i++)
        #pragma unroll
        for (int j = 0; j < TN; j++)
            acc[i][j] = 0.0f;

    const float* xb = xin + (size_t)b * CIN * HW;

    // A load mapping: 128x16 elements, 256 threads -> 8 elems each.
    // tid -> mm = tid%128 (coalesced along HW), kk = tid/128 + 2*p
    const int a_m  = tid & 127;
    const int a_k0 = tid >> 7;           // 0 or 1
    const int a_hw = hw0 + a_m;
    const bool a_ok = (a_hw < HW);

    // B load mapping: 16x64 elements, 256 threads -> 4 elems each.
    // tid -> kk = tid%16 (coalesced along K), nn = tid/16 + 16*p
    const int b_k  = tid & 15;
    const int b_n0 = tid >> 4;           // 0..15

    for (int k0 = 0; k0 < CIN; k0 += BK) {
        // ---- stage A tile [BK][BM] ----
        #pragma unroll
        for (int p = 0; p < 8; p++) {
            const int kk = a_k0 + 2 * p;
            float v = 0.0f;
            if (a_ok) v = xb[(size_t)(k0 + kk) * HW + a_hw];
            As[kk][a_m] = v;
        }
        // ---- stage B tile [BK][BN] ----
        #pragma unroll
        for (int p = 0; p < 4; p++) {
            const int nn = b_n0 + 16 * p;
            const int n  = n0 + nn;
            float v = 0.0f;
            if (n < NOUT) v = wmat[(size_t)n * CIN + (k0 + b_k)];
            Bs[b_k][nn] = v;
        }
        __syncthreads();

        // ---- compute ----
        #pragma unroll
        for (int kk = 0; kk < BK; kk++) {
            float a[TM], bb[TN];
            #pragma unroll
            for (int i = 0; i < TM; i++) a[i] = As[kk][ty * TM + i];
            #pragma unroll
            for (int j = 0; j < TN; j++) bb[j] = Bs[kk][tx * TN + j];
            #pragma unroll
            for (int i = 0; i < TM; i++)
                #pragma unroll
                for (int j = 0; j < TN; j++)
                    acc[i][j] = fmaf(a[i], bb[j], acc[i][j]);
        }
        __syncthreads();
    }

    // ---- fused YOLO decode epilogue + store ----
    #pragma unroll
    for (int i = 0; i < TM; i++) {
        const int hw = hw0 + ty * TM + i;
        if (hw >= HW) continue;
        const int h = hw / W_DIM;
        const int w = hw - h * W_DIM;
        float* orow = out + ((size_t)b * HW + hw) * NOUT;
        #pragma unroll
        for (int j = 0; j < TN; j++) {
            const int o = n0 + tx * TN + j;
            if (o >= NOUT) continue;
            float v = acc[i][j] + bias[o];
            const int a_idx = o / (NC + 5);
            const int c     = o - a_idx * (NC + 5);
            if (c == 0) {
                v = (1.0f / (1.0f + expf(-v)) + (float)w) * STRIDE_F;
            } else if (c == 1) {
                v = (1.0f / (1.0f + expf(-v)) + (float)h) * STRIDE_F;
            } else if (c == 2) {
                v = expf(v) * c_anchors[a_idx][0];
            } else if (c == 3) {
                v = expf(v) * c_anchors[a_idx][1];
            }
            orow[o] = v;
        }
    }
}

extern "C" void kernel_launch(void* const* d_in, const int* in_sizes, int n_in,
                              void* d_out, int out_size)
{
    const float* xin    = (const float*)d_in[0];   // [32, 512, 38, 38]
    const float* conv_w = (const float*)d_in[1];   // [255, 512]
    const float* conv_b = (const float*)d_in[2];   // [255]
    float* out = (float*)d_out;                    // [32, 38, 38, 3, 85]

    dim3 grid((NOUT + BN - 1) / BN,   // 4
              (HW + BM - 1) / BM,     // 12
              B_IMGS);                // 32
    yolo_fused_kernel<<<grid, NTHREADS>>>(xin, conv_w, conv_b, out);
}

// round 2
// speedup vs baseline: 1.0011x; 1.0011x over previous
#include <cuda_runtime.h>
#include <math.h>

// Problem constants (fixed by the reference)
#define B_IMGS 32
#define CIN    512
#define H_DIM  38
#define W_DIM  38
#define HW     1444          // 38*38
#define NA     3
#define NC     80
#define NOUT   255           // NA*(NC+5)
#define STRIDE_F 16.0f

// GEMM tiling
#define BM 128
#define BN 64
#define BK 16
#define TM 8
#define TN 4
#define NTHREADS 256

__constant__ float c_anchors[NA][2] = {{30.0f, 61.0f}, {62.0f, 45.0f}, {59.0f, 119.0f}};

__global__ __launch_bounds__(NTHREADS)
void yolo_fused_kernel(const float* __restrict__ xin,     // [B, CIN, HW]
                       const float* __restrict__ wmat,    // [NOUT, CIN]
                       const float* __restrict__ bias,    // [NOUT]
                       float* __restrict__ out)           // [B, HW, NOUT]
{
    const int nb = blockIdx.x;   // 0..3   (N tile)
    const int mb = blockIdx.y;   // 0..11  (HW tile)
    const int b  = blockIdx.z;   // 0..31  (image)

    const int hw0 = mb * BM;
    const int n0  = nb * BN;

    __shared__ float As[BK][BM];        // row stride 128 -> float4-aligned
    __shared__ float Bs[BK][BN + 4];    // pad 4 keeps float4 alignment

    const int tid = threadIdx.x;
    const int ty  = tid >> 4;    // 0..15 : row group (TM rows each)
    const int tx  = tid & 15;    // 0..15 : col group (TN cols each)

    float acc[TM][TN];
    #pragma unroll
    for (int i = 0; i < TM; i++)
        #pragma unroll
        for (int j = 0; j < TN; j++)
            acc[i][j] = 0.0f;

    const float* xb = xin + (size_t)b * CIN * HW;

    // A load mapping: 128x16 elements, 256 threads -> 8 elems each.
    // tid -> mm = tid%128 (coalesced along HW), kk = tid/128 + 2*p
    const int a_m  = tid & 127;
    const int a_k0 = tid >> 7;           // 0 or 1
    const int a_hw = hw0 + a_m;
    const bool a_ok = (a_hw < HW);

    // B load mapping: 16x64 elements, 256 threads -> 4 elems each.
    // tid -> kk = tid%16 (coalesced along K), nn = tid/16 + 16*p
    const int b_k  = tid & 15;
    const int b_n0 = tid >> 4;           // 0..15

    for (int k0 = 0; k0 < CIN; k0 += BK) {
        // ---- stage A tile [BK][BM] ----
        #pragma unroll
        for (int p = 0; p < 8; p++) {
            const int kk = a_k0 + 2 * p;
            float v = 0.0f;
            if (a_ok) v = xb[(size_t)(k0 + kk) * HW + a_hw];
            As[kk][a_m] = v;
        }
        // ---- stage B tile [BK][BN] ----
        #pragma unroll
        for (int p = 0; p < 4; p++) {
            const int nn = b_n0 + 16 * p;
            const int n  = n0 + nn;
            float v = 0.0f;
            if (n < NOUT) v = wmat[(size_t)n * CIN + (k0 + b_k)];
            Bs[b_k][nn] = v;
        }
        __syncthreads();

        // ---- compute ----
        #pragma unroll
        for (int kk = 0; kk < BK; kk++) {
            float a[TM], bb[TN];
            #pragma unroll
            for (int i = 0; i < TM; i++) a[i] = As[kk][ty * TM + i];
            #pragma unroll
            for (int j = 0; j < TN; j++) bb[j] = Bs[kk][tx * TN + j];
            #pragma unroll
            for (int i = 0; i < TM; i++)
                #pragma unroll
                for (int j = 0; j < TN; j++)
                    acc[i][j] = fmaf(a[i], bb[j], acc[i][j]);
        }
        __syncthreads();
    }

    // ---- fused YOLO decode epilogue + store ----
    #pragma unroll
    for (int i = 0; i < TM; i++) {
        const int hw = hw0 + ty * TM + i;
        if (hw >= HW) continue;
        const int h = hw / W_DIM;
        const int w = hw - h * W_DIM;
        float* orow = out + ((size_t)b * HW + hw) * NOUT;
        #pragma unroll
        for (int j = 0; j < TN; j++) {
            const int o = n0 + tx * TN + j;
            if (o >= NOUT) continue;
            float v = acc[i][j] + bias[o];
            const int a_idx = o / (NC + 5);
            const int c     = o - a_idx * (NC + 5);
            if (c == 0) {
                v = (1.0f / (1.0f + expf(-v)) + (float)w) * STRIDE_F;
            } else if (c == 1) {
                v = (1.0f / (1.0f + expf(-v)) + (float)h) * STRIDE_F;
            } else if (c == 2) {
                v = expf(v) * c_anchors[a_idx][0];
            } else if (c == 3) {
                v = expf(v) * c_anchors[a_idx][1];
            }
            orow[o] = v;
        }
    }
}

extern "C" void kernel_launch(void* const* d_in, const int* in_sizes, int n_in,
                              void* d_out, int out_size)
{
    const float* xin    = (const float*)d_in[0];   // [32, 512, 38, 38]
    const float* conv_w = (const float*)d_in[1];   // [255, 512]
    const float* conv_b = (const float*)d_in[2];   // [255]
    float* out = (float*)d_out;                    // [32, 38, 38, 3, 85]

    dim3 grid((NOUT + BN - 1) / BN,   // 4
              (HW + BM - 1) / BM,     // 12
              B_IMGS);                // 32
    yolo_fused_kernel<<<grid, NTHREADS>>>(xin, conv_w, conv_b, out);
}

// round 7
// speedup vs baseline: 2.0343x; 2.0321x over previous
#include <cuda_runtime.h>
#include <cuda_bf16.h>
#include <stdint.h>

// ---------------- problem constants ----------------
#define HW     1444
#define KDIM   512
#define NOUT   255
#define BM     128
#define BN     256
#define KC     32          // K per chunk
#define NCH    16          // 512 / 32
#define THREADS 512
#define NTILES 361         // 32*1444 / 128

// ---------------- smem layout (bytes) ----------------
// GEMM region (reused as output stage after compute):
//   A_hi 128x80 = 10240 @0, A_lo @10240
//   B buffers: SB(s) = 20480 + s*40960, hi @+0 (20480B), lo @+20480
// Stage: 128*255*4 = 130560 @0 (reuse). Bias @130560.
#define SA_HI   0
#define SA_LO   10240
#define SB(s)   (20480 + (s)*40960)
#define SB_LO   20480
#define S_STAGE 0
#define S_BIAS  130560
#define S_TOTAL 131584

__device__ __nv_bfloat16 g_Bhi[256 * KDIM];
__device__ __nv_bfloat16 g_Blo[256 * KDIM];

__constant__ float c_anch[3][2] = {{30.0f, 61.0f}, {62.0f, 45.0f}, {59.0f, 119.0f}};

// ---------------- helpers ----------------
static __device__ __forceinline__ uint32_t smem_u32(const void* p) {
    uint32_t a;
    asm("{ .reg .u64 t; cvta.to.shared.u64 t, %1; cvt.u32.u64 %0, t; }" : "=r"(a) : "l"(p));
    return a;
}
static __device__ __forceinline__ uint32_t pack2(__nv_bfloat16 a, __nv_bfloat16 b) {
    __nv_bfloat162 p = __halves2bfloat162(a, b);
    return *reinterpret_cast<uint32_t*>(&p);
}

#define LDM_X4(r0, r1, r2, r3, addr)                                        \
    asm volatile("ldmatrix.sync.aligned.m8n8.x4.shared.b16 {%0,%1,%2,%3}, [%4];" \
                 : "=r"(r0), "=r"(r1), "=r"(r2), "=r"(r3) : "r"(addr))

#define MMA16816(c, a, b)                                                   \
    asm volatile("mma.sync.aligned.m16n8k16.row.col.f32.bf16.bf16.f32 "     \
                 "{%0,%1,%2,%3},{%4,%5,%6,%7},{%8,%9},{%0,%1,%2,%3};"       \
                 : "+f"((c)[0]), "+f"((c)[1]), "+f"((c)[2]), "+f"((c)[3])   \
                 : "r"((a)[0]), "r"((a)[1]), "r"((a)[2]), "r"((a)[3]),      \
                   "r"((b)[0]), "r"((b)[1]))

#define CP16(dst, src)                                                      \
    asm volatile("cp.async.cg.shared.global [%0], [%1], 16;" :: "r"(dst), "l"(src))
#define CP_COMMIT() asm volatile("cp.async.commit_group;" ::: "memory")
#define CP_WAIT(n)  asm volatile("cp.async.wait_group %0;" :: "n"(n) : "memory")

// ---------------- weight prep: fp32 -> bf16 hi/lo (row-major [256][512]) ----------------
__global__ void prep_w(const float* __restrict__ w) {
    const int t = blockIdx.x * 256 + threadIdx.x;   // 131072 total
    const int n = t >> 9;
    const int k = t & 511;
    float a = (n < NOUT) ? w[n * KDIM + k] : 0.0f;
    __nv_bfloat16 h = __float2bfloat16(a);
    __nv_bfloat16 l = __float2bfloat16(a - __bfloat162float(h));
    g_Bhi[t] = h;
    g_Blo[t] = l;
}

// ---------------- main fused GEMM + YOLO decode ----------------
__global__ __launch_bounds__(THREADS)
void yolo_mma_kernel(const float* __restrict__ xin,
                     const float* __restrict__ bias,
                     float* __restrict__ out)
{
    extern __shared__ __align__(128) unsigned char smem[];
    const uint32_t sb = smem_u32(smem);
    const int tid = threadIdx.x;
    const int lid = tid & 31;
    const int wid = tid >> 5;
    const int m0  = blockIdx.x * BM;

    if (tid < NOUT) ((float*)(smem + S_BIAS))[tid] = bias[tid];

    // ----- A producer mapping (coalesced: 128 threads sweep m for fixed k) -----
    const int mA   = tid & 127;
    const int kpb  = tid >> 7;              // 0..3
    const int gm   = m0 + mA;
    const int bimg = gm / HW;
    const int hwA  = gm - bimg * HW;
    const float* xrow = xin + (size_t)bimg * KDIM * HW + hwA;
    const int sA_sw = (mA >> 3) & 3;        // 16B-column XOR key

    // ----- warp tiling -----
    const int wm = wid & 3;                 // M:  wm*32
    const int wn = wid >> 2;                // N:  wn*64
    // ldmatrix lane-address components
    const int a_r = (lid & 7) | (((lid >> 3) & 1) << 3);   // A row within 16
    const int a_c = lid >> 4;                              // A k-half (16B)
    const int b_n = (lid & 7) | ((lid >> 4) << 3);         // B n within 16
    const int b_h = (lid >> 3) & 1;                        // B k-half

    float acc[2][8][4];
    #pragma unroll
    for (int mt = 0; mt < 2; mt++)
        #pragma unroll
        for (int nt = 0; nt < 8; nt++)
            #pragma unroll
            for (int e = 0; e < 4; e++) acc[mt][nt][e] = 0.0f;

    float apf[8];

    // ---- prologue: B chunk0 cp.async, A chunk0 LDG ----
    #pragma unroll
    for (int it = 0; it < 4; it++) {
        const int idx  = it * 512 + tid;
        const int half = idx >> 10;         // 0: hi, 1: lo
        const int r    = idx & 1023;
        const int n    = r >> 2;
        const int c    = r & 3;
        const __nv_bfloat16* src = (half ? g_Blo : g_Bhi) + n * KDIM + c * 8;
        const uint32_t dst = sb + SB(0) + half * SB_LO + n * 80 + ((c ^ ((n >> 3) & 3)) << 4);
        CP16(dst, src);
    }
    CP_COMMIT();
    #pragma unroll
    for (int p = 0; p < 4; p++) {
        const int ch = 2 * (kpb + 4 * p);
        apf[2 * p]     = xrow[(size_t)ch * HW];
        apf[2 * p + 1] = xrow[(size_t)(ch + 1) * HW];
    }

    // ---- main K loop ----
    for (int i = 0; i < NCH; i++) {
        const int s = i & 1;
        __syncthreads();   // prev compute done: A buf + B buf (i+1)&1 free

        // convert + store A chunk i (from prefetch regs)
        #pragma unroll
        for (int p = 0; p < 4; p++) {
            const float a0 = apf[2 * p], a1 = apf[2 * p + 1];
            const __nv_bfloat16 h0 = __float2bfloat16(a0);
            const __nv_bfloat16 h1 = __float2bfloat16(a1);
            const __nv_bfloat16 l0 = __float2bfloat16(a0 - __bfloat162float(h0));
            const __nv_bfloat16 l1 = __float2bfloat16(a1 - __bfloat162float(h1));
            const uint32_t off = (uint32_t)(mA * 80 + ((p ^ sA_sw) << 4) + kpb * 4);
            *reinterpret_cast<uint32_t*>(smem + SA_HI + off) = pack2(h0, h1);
            *reinterpret_cast<uint32_t*>(smem + SA_LO + off) = pack2(l0, l1);
        }

        if (i + 1 < NCH) {
            // B chunk i+1 -> buffer (i+1)&1
            #pragma unroll
            for (int it = 0; it < 4; it++) {
                const int idx  = it * 512 + tid;
                const int half = idx >> 10;
                const int r    = idx & 1023;
                const int n    = r >> 2;
                const int c    = r & 3;
                const __nv_bfloat16* src = (half ? g_Blo : g_Bhi)
                                           + n * KDIM + (i + 1) * KC + c * 8;
                const uint32_t dst = sb + SB((i + 1) & 1) + half * SB_LO
                                   + n * 80 + ((c ^ ((n >> 3) & 3)) << 4);
                CP16(dst, src);
            }
            CP_COMMIT();
            // A chunk i+1 LDG prefetch
            #pragma unroll
            for (int p = 0; p < 4; p++) {
                const int ch = (i + 1) * KC + 2 * (kpb + 4 * p);
                apf[2 * p]     = xrow[(size_t)ch * HW];
                apf[2 * p + 1] = xrow[(size_t)(ch + 1) * HW];
            }
            CP_WAIT(1);    // B chunk i complete
        } else {
            CP_WAIT(0);
        }
        __syncthreads();   // A STS + B chunk i visible to all

        // ---- compute chunk i: acc += Ah*Bh + Al*Bh + Ah*Bl ----
        const uint32_t sBhi = sb + SB(s);
        const uint32_t sBlo = sBhi + SB_LO;
        #pragma unroll
        for (int ks = 0; ks < 2; ks++) {
            uint32_t Ah[2][4], Al[2][4], Bf[8][2];
            #pragma unroll
            for (int mt = 0; mt < 2; mt++) {
                const int row = wm * 32 + mt * 16 + a_r;
                const uint32_t c = (uint32_t)((ks * 2 + a_c) ^ ((row >> 3) & 3));
                LDM_X4(Ah[mt][0], Ah[mt][1], Ah[mt][2], Ah[mt][3],
                       sb + SA_HI + row * 80 + (c << 4));
            }
            #pragma unroll
            for (int np = 0; np < 4; np++) {
                const int n = wn * 64 + np * 16 + b_n;
                const uint32_t c = (uint32_t)((ks * 2 + b_h) ^ ((n >> 3) & 3));
                LDM_X4(Bf[2 * np][0], Bf[2 * np][1], Bf[2 * np + 1][0], Bf[2 * np + 1][1],
                       sBhi + n * 80 + (c << 4));
            }
            #pragma unroll
            for (int mt = 0; mt < 2; mt++)
                #pragma unroll
                for (int nt = 0; nt < 8; nt++)
                    MMA16816(acc[mt][nt], Ah[mt], Bf[nt]);

            #pragma unroll
            for (int mt = 0; mt < 2; mt++) {
                const int row = wm * 32 + mt * 16 + a_r;
                const uint32_t c = (uint32_t)((ks * 2 + a_c) ^ ((row >> 3) & 3));
                LDM_X4(Al[mt][0], Al[mt][1], Al[mt][2], Al[mt][3],
                       sb + SA_LO + row * 80 + (c << 4));
            }
            #pragma unroll
            for (int mt = 0; mt < 2; mt++)
                #pragma unroll
                for (int nt = 0; nt < 8; nt++)
                    MMA16816(acc[mt][nt], Al[mt], Bf[nt]);

            #pragma unroll
            for (int np = 0; np < 4; np++) {
                const int n = wn * 64 + np * 16 + b_n;
                const uint32_t c = (uint32_t)((ks * 2 + b_h) ^ ((n >> 3) & 3));
                LDM_X4(Bf[2 * np][0], Bf[2 * np][1], Bf[2 * np + 1][0], Bf[2 * np + 1][1],
                       sBlo + n * 80 + (c << 4));
            }
            #pragma unroll
            for (int mt = 0; mt < 2; mt++)
                #pragma unroll
                for (int nt = 0; nt < 8; nt++)
                    MMA16816(acc[mt][nt], Ah[mt], Bf[nt]);
        }
    }

    // ---- epilogue: bias + YOLO decode -> stage smem -> one bulk store ----
    __syncthreads();   // done with GEMM smem; reuse as stage
    const float* bs = (const float*)(smem + S_BIAS);
    const int g  = lid >> 2;
    const int t4 = lid & 3;

    #pragma unroll
    for (int mt = 0; mt < 2; mt++) {
        #pragma unroll
        for (int e = 0; e < 2; e++) {
            const int row = wm * 32 + mt * 16 + g + e * 8;
            const int gmr = m0 + row;
            const int bi  = gmr / HW;
            const int hw  = gmr - bi * HW;
            const int hh  = hw / 38;
            const int wwp = hw - hh * 38;
            float* srow = (float*)(smem + S_STAGE) + row * NOUT;
            #pragma unroll
            for (int nt = 0; nt < 8; nt++) {
                #pragma unroll
                for (int q = 0; q < 2; q++) {
                    const int o = wn * 64 + nt * 8 + t4 * 2 + q;
                    if (o >= NOUT) continue;
                    float v = acc[mt][nt][e * 2 + q] + bs[o];
                    const int ai = (o >= 170) ? 2 : ((o >= 85) ? 1 : 0);
                    const int c  = o - ai * 85;
                    if (c == 0)      v = (1.0f / (1.0f + __expf(-v)) + (float)wwp) * 16.0f;
                    else if (c == 1) v = (1.0f / (1.0f + __expf(-v)) + (float)hh) * 16.0f;
                    else if (c == 2) v = __expf(v) * c_anch[ai][0];
                    else if (c == 3) v = __expf(v) * c_anch[ai][1];
                    srow[o] = v;
                }
            }
        }
    }
    __syncthreads();

    if (tid == 0) {
        asm volatile("fence.proxy.async;" ::: "memory");
        float* gdst = out + (size_t)m0 * NOUT;
        asm volatile("cp.async.bulk.global.shared::cta.bulk_group [%0], [%1], %2;"
                     :: "l"(gdst), "r"(sb + S_STAGE), "r"((uint32_t)(BM * NOUT * 4)) : "memory");
        asm volatile("cp.async.bulk.commit_group;" ::: "memory");
        asm volatile("cp.async.bulk.wait_group 0;" ::: "memory");
    }
}

extern "C" void kernel_launch(void* const* d_in, const int* in_sizes, int n_in,
                              void* d_out, int out_size)
{
    const float* xin    = (const float*)d_in[0];   // [32, 512, 38, 38]
    const float* conv_w = (const float*)d_in[1];   // [255, 512]
    const float* conv_b = (const float*)d_in[2];   // [255]
    float* out = (float*)d_out;                    // [32, 38, 38, 3, 85]

    cudaFuncSetAttribute(yolo_mma_kernel,
                         cudaFuncAttributeMaxDynamicSharedMemorySize, S_TOTAL);

    prep_w<<<512, 256>>>(conv_w);
    yolo_mma_kernel<<<NTILES, THREADS, S_TOTAL>>>(xin, conv_b, out);
}

// round 9
// speedup vs baseline: 2.4637x; 1.2111x over previous
#include <cuda_runtime.h>
#include <cuda_bf16.h>
#include <stdint.h>

// ---------------- problem constants ----------------
#define HW     1444
#define KDIM   512
#define NOUT   255
#define BM     64
#define BN     256
#define KC     32          // K per chunk
#define NCH    16          // 512 / 32
#define THREADS 256
#define NTILES 722         // 32*1444 / 64

// ---------------- smem layout (bytes) ----------------
// A buffers (double): hi/lo per stage, 64 rows x 80 B
//   SA_HI(s) = s*10240, SA_LO(s) = s*10240 + 5120          (A: 0..20480)
// B buffers (double): 256 rows x 80 B per half = 20480 B
//   SBF(s) = 20480 + s*40960; hi @+0, lo @+20480           (B: 20480..102400)
// Bias @102400. Stage (reuse @0): 64*255*4 = 65280.
#define SA_HI(s) ((s)*10240)
#define SA_LO(s) ((s)*10240 + 5120)
#define SBF(s)   (20480 + (s)*40960)
#define SB_LO    20480
#define S_STAGE  0
#define S_BIAS   102400
#define S_TOTAL  103424

__device__ __nv_bfloat16 g_Bhi[256 * KDIM];
__device__ __nv_bfloat16 g_Blo[256 * KDIM];

__constant__ float c_anch[3][2] = {{30.0f, 61.0f}, {62.0f, 45.0f}, {59.0f, 119.0f}};

// ---------------- helpers ----------------
static __device__ __forceinline__ uint32_t smem_u32(const void* p) {
    uint32_t a;
    asm("{ .reg .u64 t; cvta.to.shared.u64 t, %1; cvt.u32.u64 %0, t; }" : "=r"(a) : "l"(p));
    return a;
}
static __device__ __forceinline__ uint32_t pack2(__nv_bfloat16 a, __nv_bfloat16 b) {
    __nv_bfloat162 p = __halves2bfloat162(a, b);
    return *reinterpret_cast<uint32_t*>(&p);
}

#define LDM_X4(r0, r1, r2, r3, addr)                                        \
    asm volatile("ldmatrix.sync.aligned.m8n8.x4.shared.b16 {%0,%1,%2,%3}, [%4];" \
                 : "=r"(r0), "=r"(r1), "=r"(r2), "=r"(r3) : "r"(addr))

#define MMA16816(c, a, b)                                                   \
    asm volatile("mma.sync.aligned.m16n8k16.row.col.f32.bf16.bf16.f32 "     \
                 "{%0,%1,%2,%3},{%4,%5,%6,%7},{%8,%9},{%0,%1,%2,%3};"       \
                 : "+f"((c)[0]), "+f"((c)[1]), "+f"((c)[2]), "+f"((c)[3])   \
                 : "r"((a)[0]), "r"((a)[1]), "r"((a)[2]), "r"((a)[3]),      \
                   "r"((b)[0]), "r"((b)[1]))

#define CP16(dst, src)                                                      \
    asm volatile("cp.async.cg.shared.global [%0], [%1], 16;" :: "r"(dst), "l"(src))
#define CP_COMMIT() asm volatile("cp.async.commit_group;" ::: "memory")
#define CP_WAIT0()  asm volatile("cp.async.wait_group 0;" ::: "memory")

// ---------------- weight prep: fp32 -> bf16 hi/lo (row-major [256][512]) ----------------
__global__ void prep_w(const float* __restrict__ w) {
    const int t = blockIdx.x * 256 + threadIdx.x;   // 131072 total
    const int n = t >> 9;
    const int k = t & 511;
    float a = (n < NOUT) ? w[n * KDIM + k] : 0.0f;
    __nv_bfloat16 h = __float2bfloat16(a);
    __nv_bfloat16 l = __float2bfloat16(a - __bfloat162float(h));
    g_Bhi[t] = h;
    g_Blo[t] = l;
}

// ---------------- main fused GEMM + YOLO decode ----------------
__global__ __launch_bounds__(THREADS, 2)
void yolo_mma_kernel(const float* __restrict__ xin,
                     const float* __restrict__ bias,
                     float* __restrict__ out)
{
    extern __shared__ __align__(128) unsigned char smem[];
    const uint32_t sb = smem_u32(smem);
    const int tid = threadIdx.x;
    const int lid = tid & 31;
    const int wid = tid >> 5;
    const int m0  = blockIdx.x * BM;

    if (tid < NOUT) ((float*)(smem + S_BIAS))[tid] = bias[tid];

    // ----- A producer mapping (coalesced: 64 threads sweep m for fixed k) -----
    const int mA   = tid & 63;
    const int kpb  = tid >> 6;              // 0..3
    const int gm   = m0 + mA;
    const int bimg = gm / HW;
    const int hwA  = gm - bimg * HW;
    const float* xrow = xin + (size_t)bimg * KDIM * HW + hwA;
    const int sA_sw = (mA >> 3) & 3;        // 16B-column XOR key

    // ----- warp tiling: 8 warps, 2 (M) x 4 (N), warp tile 32x64 -----
    const int wm = wid & 1;
    const int wn = wid >> 1;
    const int a_r = (lid & 7) | (((lid >> 3) & 1) << 3);
    const int a_c = lid >> 4;
    const int b_n = (lid & 7) | ((lid >> 4) << 3);
    const int b_h = (lid >> 3) & 1;

    float acc[2][8][4];
    #pragma unroll
    for (int mt = 0; mt < 2; mt++)
        #pragma unroll
        for (int nt = 0; nt < 8; nt++)
            #pragma unroll
            for (int e = 0; e < 4; e++) acc[mt][nt][e] = 0.0f;

    float apf[8];

    // ---- prologue: B chunk0 cp.async, A chunk0 LDG ----
    #pragma unroll
    for (int it = 0; it < 8; it++) {
        const int idx  = it * 256 + tid;    // 2048 x 16B
        const int half = idx >> 10;
        const int r    = idx & 1023;
        const int n    = r >> 2;
        const int c    = r & 3;
        const __nv_bfloat16* src = (half ? g_Blo : g_Bhi) + n * KDIM + c * 8;
        const uint32_t dst = sb + SBF(0) + half * SB_LO + n * 80 + ((c ^ ((n >> 3) & 3)) << 4);
        CP16(dst, src);
    }
    CP_COMMIT();
    #pragma unroll
    for (int p = 0; p < 4; p++) {
        const int ch = 2 * (kpb + 4 * p);
        apf[2 * p]     = xrow[(size_t)ch * HW];
        apf[2 * p + 1] = xrow[(size_t)(ch + 1) * HW];
    }

    // ---- main K loop: ONE sync per chunk ----
    for (int i = 0; i < NCH; i++) {
        const int s = i & 1;

        // STS A chunk i into buffer s (safe: sync(i-1) ordered all warps past compute(i-2))
        #pragma unroll
        for (int p = 0; p < 4; p++) {
            const float a0 = apf[2 * p], a1 = apf[2 * p + 1];
            const __nv_bfloat16 h0 = __float2bfloat16(a0);
            const __nv_bfloat16 h1 = __float2bfloat16(a1);
            const __nv_bfloat16 l0 = __float2bfloat16(a0 - __bfloat162float(h0));
            const __nv_bfloat16 l1 = __float2bfloat16(a1 - __bfloat162float(h1));
            const uint32_t off = (uint32_t)(mA * 80 + ((p ^ sA_sw) << 4) + kpb * 4);
            *reinterpret_cast<uint32_t*>(smem + SA_HI(s) + off) = pack2(h0, h1);
            *reinterpret_cast<uint32_t*>(smem + SA_LO(s) + off) = pack2(l0, l1);
        }

        CP_WAIT0();        // B chunk i landed
        __syncthreads();   // A(i) + B(i) visible; all warps done compute(i-1)

        if (i + 1 < NCH) {
            // issue B chunk i+1 into buffer !s (safe: everyone past compute(i-1))
            #pragma unroll
            for (int it = 0; it < 8; it++) {
                const int idx  = it * 256 + tid;
                const int half = idx >> 10;
                const int r    = idx & 1023;
                const int n    = r >> 2;
                const int c    = r & 3;
                const __nv_bfloat16* src = (half ? g_Blo : g_Bhi)
                                           + n * KDIM + (i + 1) * KC + c * 8;
                const uint32_t dst = sb + SBF((i + 1) & 1) + half * SB_LO
                                   + n * 80 + ((c ^ ((n >> 3) & 3)) << 4);
                CP16(dst, src);
            }
            CP_COMMIT();
            // A chunk i+1 LDG prefetch (consumed next iteration)
            #pragma unroll
            for (int p = 0; p < 4; p++) {
                const int ch = (i + 1) * KC + 2 * (kpb + 4 * p);
                apf[2 * p]     = xrow[(size_t)ch * HW];
                apf[2 * p + 1] = xrow[(size_t)(ch + 1) * HW];
            }
        }

        // ---- compute chunk i: acc += Ah*Bh + Al*Bh + Ah*Bl ----
        const uint32_t sBhi = sb + SBF(s);
        const uint32_t sBlo = sBhi + SB_LO;
        #pragma unroll
        for (int ks = 0; ks < 2; ks++) {
            uint32_t Ah[2][4], Al[2][4], Bf[8][2];
            #pragma unroll
            for (int mt = 0; mt < 2; mt++) {
                const int row = wm * 32 + mt * 16 + a_r;
                const uint32_t c = (uint32_t)((ks * 2 + a_c) ^ ((row >> 3) & 3));
                LDM_X4(Ah[mt][0], Ah[mt][1], Ah[mt][2], Ah[mt][3],
                       sb + SA_HI(s) + row * 80 + (c << 4));
            }
            #pragma unroll
            for (int np = 0; np < 4; np++) {
                const int n = wn * 64 + np * 16 + b_n;
                const uint32_t c = (uint32_t)((ks * 2 + b_h) ^ ((n >> 3) & 3));
                LDM_X4(Bf[2 * np][0], Bf[2 * np][1], Bf[2 * np + 1][0], Bf[2 * np + 1][1],
                       sBhi + n * 80 + (c << 4));
            }
            #pragma unroll
            for (int mt = 0; mt < 2; mt++)
                #pragma unroll
                for (int nt = 0; nt < 8; nt++)
                    MMA16816(acc[mt][nt], Ah[mt], Bf[nt]);

            #pragma unroll
            for (int mt = 0; mt < 2; mt++) {
                const int row = wm * 32 + mt * 16 + a_r;
                const uint32_t c = (uint32_t)((ks * 2 + a_c) ^ ((row >> 3) & 3));
                LDM_X4(Al[mt][0], Al[mt][1], Al[mt][2], Al[mt][3],
                       sb + SA_LO(s) + row * 80 + (c << 4));
            }
            #pragma unroll
            for (int mt = 0; mt < 2; mt++)
                #pragma unroll
                for (int nt = 0; nt < 8; nt++)
                    MMA16816(acc[mt][nt], Al[mt], Bf[nt]);

            #pragma unroll
            for (int np = 0; np < 4; np++) {
                const int n = wn * 64 + np * 16 + b_n;
                const uint32_t c = (uint32_t)((ks * 2 + b_h) ^ ((n >> 3) & 3));
                LDM_X4(Bf[2 * np][0], Bf[2 * np][1], Bf[2 * np + 1][0], Bf[2 * np + 1][1],
                       sBlo + n * 80 + (c << 4));
            }
            #pragma unroll
            for (int mt = 0; mt < 2; mt++)
                #pragma unroll
                for (int nt = 0; nt < 8; nt++)
                    MMA16816(acc[mt][nt], Ah[mt], Bf[nt]);
        }
    }

    // ---- epilogue: bias + YOLO decode -> stage smem -> one bulk store ----
    __syncthreads();   // done with GEMM smem; reuse as stage
    const float* bs = (const float*)(smem + S_BIAS);
    const int g  = lid >> 2;
    const int t4 = lid & 3;

    #pragma unroll
    for (int mt = 0; mt < 2; mt++) {
        #pragma unroll
        for (int e = 0; e < 2; e++) {
            const int row = wm * 32 + mt * 16 + g + e * 8;
            const int gmr = m0 + row;
            const int bi  = gmr / HW;
            const int hw  = gmr - bi * HW;
            const int hh  = hw / 38;
            const int wwp = hw - hh * 38;
            float* srow = (float*)(smem + S_STAGE) + row * NOUT;
            #pragma unroll
            for (int nt = 0; nt < 8; nt++) {
                #pragma unroll
                for (int q = 0; q < 2; q++) {
                    const int o = wn * 64 + nt * 8 + t4 * 2 + q;
                    if (o >= NOUT) continue;
                    float v = acc[mt][nt][e * 2 + q] + bs[o];
                    const int ai = (o >= 170) ? 2 : ((o >= 85) ? 1 : 0);
                    const int c  = o - ai * 85;
                    if (c == 0)      v = (1.0f / (1.0f + __expf(-v)) + (float)wwp) * 16.0f;
                    else if (c == 1) v = (1.0f / (1.0f + __expf(-v)) + (float)hh) * 16.0f;
                    else if (c == 2) v = __expf(v) * c_anch[ai][0];
                    else if (c == 3) v = __expf(v) * c_anch[ai][1];
                    srow[o] = v;
                }
            }
        }
    }
    __syncthreads();

    if (tid == 0) {
        asm volatile("fence.proxy.async;" ::: "memory");
        float* gdst = out + (size_t)m0 * NOUT;
        asm volatile("cp.async.bulk.global.shared::cta.bulk_group [%0], [%1], %2;"
                     :: "l"(gdst), "r"(sb + S_STAGE), "r"((uint32_t)(BM * NOUT * 4)) : "memory");
        asm volatile("cp.async.bulk.commit_group;" ::: "memory");
        asm volatile("cp.async.bulk.wait_group 0;" ::: "memory");
    }
}

extern "C" void kernel_launch(void* const* d_in, const int* in_sizes, int n_in,
                              void* d_out, int out_size)
{
    const float* xin    = (const float*)d_in[0];   // [32, 512, 38, 38]
    const float* conv_w = (const float*)d_in[1];   // [255, 512]
    const float* conv_b = (const float*)d_in[2];   // [255]
    float* out = (float*)d_out;                    // [32, 38, 38, 3, 85]

    cudaFuncSetAttribute(yolo_mma_kernel,
                         cudaFuncAttributeMaxDynamicSharedMemorySize, S_TOTAL);

    prep_w<<<512, 256>>>(conv_w);
    yolo_mma_kernel<<<NTILES, THREADS, S_TOTAL>>>(xin, conv_b, out);
}

// round 10
// speedup vs baseline: 3.3971x; 1.3789x over previous
#include <cuda_runtime.h>
#include <cuda_fp16.h>
#include <stdint.h>

// ---------------- problem constants ----------------
#define HW     1444
#define KDIM   512
#define NOUT   255
#define BM     64
#define BN     256
#define KC     32          // K per chunk
#define NCH    16          // 512 / 32
#define THREADS 256
#define NTILES 722         // 32*1444 / 64

// ---------------- smem layout (bytes) ----------------
// A buffers (double): hi/lo per stage, 64 rows x 80 B   (A: 0..20480)
// B buffers (triple): 256 rows x 80 B per stage          (B: 20480..81920)
// Bias @81920. Stage (reuse @0): 64*255*4 = 65280.
#define SA_HI(s) ((s)*10240)
#define SA_LO(s) ((s)*10240 + 5120)
#define SBF(st)  (20480 + (st)*20480)
#define S_STAGE  0
#define S_BIAS   81920
#define S_TOTAL  82944

__device__ __half g_Bh[256 * KDIM];

__constant__ float c_anch[3][2] = {{30.0f, 61.0f}, {62.0f, 45.0f}, {59.0f, 119.0f}};

// ---------------- helpers ----------------
static __device__ __forceinline__ uint32_t smem_u32(const void* p) {
    uint32_t a;
    asm("{ .reg .u64 t; cvta.to.shared.u64 t, %1; cvt.u32.u64 %0, t; }" : "=r"(a) : "l"(p));
    return a;
}
static __device__ __forceinline__ uint32_t pack2h(__half a, __half b) {
    __half2 p = __halves2half2(a, b);
    return *reinterpret_cast<uint32_t*>(&p);
}

#define LDM_X4(r0, r1, r2, r3, addr)                                        \
    asm volatile("ldmatrix.sync.aligned.m8n8.x4.shared.b16 {%0,%1,%2,%3}, [%4];" \
                 : "=r"(r0), "=r"(r1), "=r"(r2), "=r"(r3) : "r"(addr))

#define MMA16816(c, a, b)                                                   \
    asm volatile("mma.sync.aligned.m16n8k16.row.col.f32.f16.f16.f32 "       \
                 "{%0,%1,%2,%3},{%4,%5,%6,%7},{%8,%9},{%0,%1,%2,%3};"       \
                 : "+f"((c)[0]), "+f"((c)[1]), "+f"((c)[2]), "+f"((c)[3])   \
                 : "r"((a)[0]), "r"((a)[1]), "r"((a)[2]), "r"((a)[3]),      \
                   "r"((b)[0]), "r"((b)[1]))

#define CP16(dst, src)                                                      \
    asm volatile("cp.async.cg.shared.global [%0], [%1], 16;" :: "r"(dst), "l"(src))
#define CP_COMMIT() asm volatile("cp.async.commit_group;" ::: "memory")
#define CP_WAIT1()  asm volatile("cp.async.wait_group 1;" ::: "memory")
#define CP_WAIT0()  asm volatile("cp.async.wait_group 0;" ::: "memory")

// ---------------- weight prep: fp32 -> fp16 (row-major [256][512]) ----------------
__global__ void prep_w(const float* __restrict__ w) {
    const int t = blockIdx.x * 256 + threadIdx.x;   // 131072 total
    const int n = t >> 9;
    const int k = t & 511;
    float a = (n < NOUT) ? w[n * KDIM + k] : 0.0f;
    g_Bh[t] = __float2half_rn(a);
}

// ---------------- B chunk issue (1024 x 16B via cp.async) ----------------
static __device__ __forceinline__ void issue_B(uint32_t sb, int tid, int chunk) {
    const int st = chunk % 3;
    #pragma unroll
    for (int it = 0; it < 4; it++) {
        const int idx = it * 256 + tid;          // 0..1023
        const int n   = idx >> 2;
        const int c   = idx & 3;
        const __half* src = g_Bh + n * KDIM + chunk * KC + c * 8;
        const uint32_t dst = sb + SBF(st) + n * 80 + ((c ^ ((n >> 3) & 3)) << 4);
        CP16(dst, src);
    }
    CP_COMMIT();
}

// ---------------- main fused GEMM + YOLO decode ----------------
__global__ __launch_bounds__(THREADS, 2)
void yolo_mma_kernel(const float* __restrict__ xin,
                     const float* __restrict__ bias,
                     float* __restrict__ out)
{
    extern __shared__ __align__(128) unsigned char smem[];
    const uint32_t sb = smem_u32(smem);
    const int tid = threadIdx.x;
    const int lid = tid & 31;
    const int wid = tid >> 5;
    const int m0  = blockIdx.x * BM;

    if (tid < NOUT) ((float*)(smem + S_BIAS))[tid] = bias[tid];

    // ----- A producer mapping (coalesced: 64 threads sweep m for fixed k) -----
    const int mA   = tid & 63;
    const int kpb  = tid >> 6;              // 0..3
    const int gm   = m0 + mA;
    const int bimg = gm / HW;
    const int hwA  = gm - bimg * HW;
    const float* xrow = xin + (size_t)bimg * KDIM * HW + hwA;
    const int sA_sw = (mA >> 3) & 3;        // 16B-column XOR key

    // ----- warp tiling: 8 warps, 2 (M) x 4 (N), warp tile 32x64 -----
    const int wm = wid & 1;
    const int wn = wid >> 1;
    const int a_r = (lid & 7) | (((lid >> 3) & 1) << 3);
    const int a_c = lid >> 4;
    const int b_n = (lid & 7) | ((lid >> 4) << 3);
    const int b_h = (lid >> 3) & 1;

    float acc[2][8][4];
    #pragma unroll
    for (int mt = 0; mt < 2; mt++)
        #pragma unroll
        for (int nt = 0; nt < 8; nt++)
            #pragma unroll
            for (int e = 0; e < 4; e++) acc[mt][nt][e] = 0.0f;

    float apf[8];

    // ---- prologue: B chunk 0 and 1 in flight, A chunk 0 LDG ----
    issue_B(sb, tid, 0);
    issue_B(sb, tid, 1);
    #pragma unroll
    for (int p = 0; p < 4; p++) {
        const int ch = 2 * (kpb + 4 * p);
        apf[2 * p]     = xrow[(size_t)ch * HW];
        apf[2 * p + 1] = xrow[(size_t)(ch + 1) * HW];
    }

    // ---- main K loop: ONE sync per chunk, 3-stage B pipeline ----
    for (int i = 0; i < NCH; i++) {
        const int s  = i & 1;
        const int st = i % 3;

        // STS A chunk i (fp16 hi + fp16 residual) into buffer s
        #pragma unroll
        for (int p = 0; p < 4; p++) {
            const float a0 = apf[2 * p], a1 = apf[2 * p + 1];
            const __half h0 = __float2half_rn(a0);
            const __half h1 = __float2half_rn(a1);
            const __half l0 = __float2half_rn(a0 - __half2float(h0));
            const __half l1 = __float2half_rn(a1 - __half2float(h1));
            const uint32_t off = (uint32_t)(mA * 80 + ((p ^ sA_sw) << 4) + kpb * 4);
            *reinterpret_cast<uint32_t*>(smem + SA_HI(s) + off) = pack2h(h0, h1);
            *reinterpret_cast<uint32_t*>(smem + SA_LO(s) + off) = pack2h(l0, l1);
        }

        if (i < NCH - 1) { CP_WAIT1(); }    // B(i) done (issued 2 chunks ago)
        else            { CP_WAIT0(); }
        __syncthreads();                     // A(i)+B(i) visible; all past compute(i-1)

        if (i + 2 < NCH) issue_B(sb, tid, i + 2);   // stage (i+2)%3 free since sync
        if (i + 1 < NCH) {
            #pragma unroll
            for (int p = 0; p < 4; p++) {
                const int ch = (i + 1) * KC + 2 * (kpb + 4 * p);
                apf[2 * p]     = xrow[(size_t)ch * HW];
                apf[2 * p + 1] = xrow[(size_t)(ch + 1) * HW];
            }
        }

        // ---- compute chunk i: acc += Ah*B + Al*B ----
        const uint32_t sB = sb + SBF(st);
        #pragma unroll
        for (int ks = 0; ks < 2; ks++) {
            uint32_t Ah[2][4], Al[2][4], Bf[8][2];
            #pragma unroll
            for (int mt = 0; mt < 2; mt++) {
                const int row = wm * 32 + mt * 16 + a_r;
                const uint32_t c = (uint32_t)((ks * 2 + a_c) ^ ((row >> 3) & 3));
                LDM_X4(Ah[mt][0], Ah[mt][1], Ah[mt][2], Ah[mt][3],
                       sb + SA_HI(s) + row * 80 + (c << 4));
            }
            #pragma unroll
            for (int np = 0; np < 4; np++) {
                const int n = wn * 64 + np * 16 + b_n;
                const uint32_t c = (uint32_t)((ks * 2 + b_h) ^ ((n >> 3) & 3));
                LDM_X4(Bf[2 * np][0], Bf[2 * np][1], Bf[2 * np + 1][0], Bf[2 * np + 1][1],
                       sB + n * 80 + (c << 4));
            }
            #pragma unroll
            for (int mt = 0; mt < 2; mt++) {
                const int row = wm * 32 + mt * 16 + a_r;
                const uint32_t c = (uint32_t)((ks * 2 + a_c) ^ ((row >> 3) & 3));
                LDM_X4(Al[mt][0], Al[mt][1], Al[mt][2], Al[mt][3],
                       sb + SA_LO(s) + row * 80 + (c << 4));
            }
            #pragma unroll
            for (int mt = 0; mt < 2; mt++)
                #pragma unroll
                for (int nt = 0; nt < 8; nt++)
                    MMA16816(acc[mt][nt], Ah[mt], Bf[nt]);
            #pragma unroll
            for (int mt = 0; mt < 2; mt++)
                #pragma unroll
                for (int nt = 0; nt < 8; nt++)
                    MMA16816(acc[mt][nt], Al[mt], Bf[nt]);
        }
    }

    // ---- epilogue: bias + YOLO decode -> stage smem -> one bulk store ----
    __syncthreads();   // done with GEMM smem; reuse as stage
    const float* bs = (const float*)(smem + S_BIAS);
    const int g  = lid >> 2;
    const int t4 = lid & 3;

    #pragma unroll
    for (int mt = 0; mt < 2; mt++) {
        #pragma unroll
        for (int e = 0; e < 2; e++) {
            const int row = wm * 32 + mt * 16 + g + e * 8;
            const int gmr = m0 + row;
            const int bi  = gmr / HW;
            const int hw  = gmr - bi * HW;
            const int hh  = hw / 38;
            const int wwp = hw - hh * 38;
            float* srow = (float*)(smem + S_STAGE) + row * NOUT;
            #pragma unroll
            for (int nt = 0; nt < 8; nt++) {
                #pragma unroll
                for (int q = 0; q < 2; q++) {
                    const int o = wn * 64 + nt * 8 + t4 * 2 + q;
                    if (o >= NOUT) continue;
                    float v = acc[mt][nt][e * 2 + q] + bs[o];
                    const int ai = (o >= 170) ? 2 : ((o >= 85) ? 1 : 0);
                    const int c  = o - ai * 85;
                    if (c == 0)      v = (1.0f / (1.0f + __expf(-v)) + (float)wwp) * 16.0f;
                    else if (c == 1) v = (1.0f / (1.0f + __expf(-v)) + (float)hh) * 16.0f;
                    else if (c == 2) v = __expf(v) * c_anch[ai][0];
                    else if (c == 3) v = __expf(v) * c_anch[ai][1];
                    srow[o] = v;
                }
            }
        }
    }
    __syncthreads();

    if (tid == 0) {
        asm volatile("fence.proxy.async;" ::: "memory");
        float* gdst = out + (size_t)m0 * NOUT;
        asm volatile("cp.async.bulk.global.shared::cta.bulk_group [%0], [%1], %2;"
                     :: "l"(gdst), "r"(sb + S_STAGE), "r"((uint32_t)(BM * NOUT * 4)) : "memory");
        asm volatile("cp.async.bulk.commit_group;" ::: "memory");
        asm volatile("cp.async.bulk.wait_group 0;" ::: "memory");
    }
}

extern "C" void kernel_launch(void* const* d_in, const int* in_sizes, int n_in,
                              void* d_out, int out_size)
{
    const float* xin    = (const float*)d_in[0];   // [32, 512, 38, 38]
    const float* conv_w = (const float*)d_in[1];   // [255, 512]
    const float* conv_b = (const float*)d_in[2];   // [255]
    float* out = (float*)d_out;                    // [32, 38, 38, 3, 85]

    cudaFuncSetAttribute(yolo_mma_kernel,
                         cudaFuncAttributeMaxDynamicSharedMemorySize, S_TOTAL);

    prep_w<<<512, 256>>>(conv_w);
    yolo_mma_kernel<<<NTILES, THREADS, S_TOTAL>>>(xin, conv_b, out);
}

// round 11
// speedup vs baseline: 4.1584x; 1.2241x over previous
#include <cuda_runtime.h>
#include <cuda_fp16.h>
#include <stdint.h>

// ---------------- problem constants ----------------
#define HW     1444
#define KDIM   512
#define NOUT   255
#define BM     64
#define BN     256
#define KC     64          // K per chunk
#define NCH    8           // 512 / 64
#define THREADS 256
#define NTILES 722         // 32*1444 / 64

// ---------------- smem layout (bytes) ----------------
// A (double): 64 rows x 128 B, XOR-swizzled             (0..32768)
// B (double): 256 rows x 128 B, XOR-swizzled            (32768..98304)
// Bias @98304. Stage (reuse @0): 64*255*4 = 65280.
#define SA(s)   ((s)*16384)
#define SBF(s)  (32768 + (s)*32768)
#define S_STAGE 0
#define S_BIAS  98304
#define S_TOTAL 99328

__device__ __half g_Bh[256 * KDIM];

__constant__ float c_anch[3][2] = {{30.0f, 61.0f}, {62.0f, 45.0f}, {59.0f, 119.0f}};

// ---------------- helpers ----------------
static __device__ __forceinline__ uint32_t smem_u32(const void* p) {
    uint32_t a;
    asm("{ .reg .u64 t; cvta.to.shared.u64 t, %1; cvt.u32.u64 %0, t; }" : "=r"(a) : "l"(p));
    return a;
}
static __device__ __forceinline__ uint32_t pack2h(__half a, __half b) {
    __half2 p = __halves2half2(a, b);
    return *reinterpret_cast<uint32_t*>(&p);
}

#define LDM_X4(r0, r1, r2, r3, addr)                                        \
    asm volatile("ldmatrix.sync.aligned.m8n8.x4.shared.b16 {%0,%1,%2,%3}, [%4];" \
                 : "=r"(r0), "=r"(r1), "=r"(r2), "=r"(r3) : "r"(addr))

#define MMA16816(c, a, b)                                                   \
    asm volatile("mma.sync.aligned.m16n8k16.row.col.f32.f16.f16.f32 "       \
                 "{%0,%1,%2,%3},{%4,%5,%6,%7},{%8,%9},{%0,%1,%2,%3};"       \
                 : "+f"((c)[0]), "+f"((c)[1]), "+f"((c)[2]), "+f"((c)[3])   \
                 : "r"((a)[0]), "r"((a)[1]), "r"((a)[2]), "r"((a)[3]),      \
                   "r"((b)[0]), "r"((b)[1]))

#define CP16(dst, src)                                                      \
    asm volatile("cp.async.cg.shared.global [%0], [%1], 16;" :: "r"(dst), "l"(src))
#define CP_COMMIT() asm volatile("cp.async.commit_group;" ::: "memory")
#define CP_WAIT0()  asm volatile("cp.async.wait_group 0;" ::: "memory")

// ---------------- weight prep: fp32 -> fp16 (row-major [256][512]) ----------------
__global__ void prep_w(const float* __restrict__ w) {
    const int t = blockIdx.x * 256 + threadIdx.x;   // 131072 total
    const int n = t >> 9;
    const int k = t & 511;
    float a = (n < NOUT) ? w[n * KDIM + k] : 0.0f;
    g_Bh[t] = __float2half_rn(a);
}

// ---------------- B chunk issue (2048 x 16B via cp.async, 8/thread) ----------------
static __device__ __forceinline__ void issue_B(uint32_t sb, int tid, int chunk) {
    const uint32_t base = sb + SBF(chunk & 1);
    #pragma unroll
    for (int it = 0; it < 8; it++) {
        const int idx = it * 256 + tid;          // 0..2047
        const int n   = idx >> 3;
        const int c   = idx & 7;
        const __half* src = g_Bh + n * KDIM + chunk * KC + c * 8;
        const uint32_t dst = base + n * 128 + ((c ^ (n & 7)) << 4);
        CP16(dst, src);
    }
    CP_COMMIT();
}

// ---------------- main fused GEMM + YOLO decode ----------------
__global__ __launch_bounds__(THREADS, 2)
void yolo_mma_kernel(const float* __restrict__ xin,
                     const float* __restrict__ bias,
                     float* __restrict__ out)
{
    extern __shared__ __align__(128) unsigned char smem[];
    const uint32_t sb = smem_u32(smem);
    const int tid = threadIdx.x;
    const int lid = tid & 31;
    const int wid = tid >> 5;
    const int m0  = blockIdx.x * BM;

    if (tid < NOUT) ((float*)(smem + S_BIAS))[tid] = bias[tid];

    // ----- A producer mapping (coalesced: 64 threads sweep m for fixed k) -----
    const int mA   = tid & 63;
    const int kq   = tid >> 6;              // 0..3
    const int gm   = m0 + mA;
    const int bimg = gm / HW;
    const int hwA  = gm - bimg * HW;
    const float* xrow = xin + (size_t)bimg * KDIM * HW + hwA;
    const int aKey = mA & 7;                // XOR swizzle key for this row

    // ----- warp tiling: 8 warps, 2 (M) x 4 (N), warp tile 32x64 -----
    const int wm = wid & 1;
    const int wn = wid >> 1;
    const int a_r = (lid & 7) | (((lid >> 3) & 1) << 3);
    const int a_c = lid >> 4;
    const int b_n = (lid & 7) | ((lid >> 4) << 3);
    const int b_h = (lid >> 3) & 1;

    float acc[2][8][4];
    #pragma unroll
    for (int mt = 0; mt < 2; mt++)
        #pragma unroll
        for (int nt = 0; nt < 8; nt++)
            #pragma unroll
            for (int e = 0; e < 4; e++) acc[mt][nt][e] = 0.0f;

    float apf[16];

    // ---- prologue: B chunk 0 in flight, A chunk 0 LDG ----
    issue_B(sb, tid, 0);
    #pragma unroll
    for (int j = 0; j < 8; j++) {
        const int k = 2 * (kq + 4 * j);
        apf[2 * j]     = xrow[(size_t)k * HW];
        apf[2 * j + 1] = xrow[(size_t)(k + 1) * HW];
    }

    // ---- main K loop: ONE sync per chunk (8 chunks) ----
    for (int i = 0; i < NCH; i++) {
        const int s = i & 1;

        // STS A chunk i (fp16) into buffer s
        #pragma unroll
        for (int j = 0; j < 8; j++) {
            const __half h0 = __float2half_rn(apf[2 * j]);
            const __half h1 = __float2half_rn(apf[2 * j + 1]);
            const uint32_t off = (uint32_t)(mA * 128 + ((j ^ aKey) << 4) + kq * 4);
            *reinterpret_cast<uint32_t*>(smem + SA(s) + off) = pack2h(h0, h1);
        }

        CP_WAIT0();        // B chunk i landed (issued a full chunk ago)
        __syncthreads();   // A(i)+B(i) visible; all warps past compute(i-1)

        if (i + 1 < NCH) {
            issue_B(sb, tid, i + 1);   // buffer !s free since sync
            #pragma unroll
            for (int j = 0; j < 8; j++) {
                const int k = (i + 1) * KC + 2 * (kq + 4 * j);
                apf[2 * j]     = xrow[(size_t)k * HW];
                apf[2 * j + 1] = xrow[(size_t)(k + 1) * HW];
            }
        }

        // ---- compute chunk i: acc += A*B (pure fp16, 4 k-steps of 16) ----
        const uint32_t sA = sb + SA(s);
        const uint32_t sB = sb + SBF(s);
        #pragma unroll
        for (int ks = 0; ks < 4; ks++) {
            uint32_t Ah[2][4], Bf[8][2];
            #pragma unroll
            for (int mt = 0; mt < 2; mt++) {
                const int row = wm * 32 + mt * 16 + a_r;
                const uint32_t c = (uint32_t)((ks * 2 + a_c) ^ (row & 7));
                LDM_X4(Ah[mt][0], Ah[mt][1], Ah[mt][2], Ah[mt][3],
                       sA + row * 128 + (c << 4));
            }
            #pragma unroll
            for (int np = 0; np < 4; np++) {
                const int n = wn * 64 + np * 16 + b_n;
                const uint32_t c = (uint32_t)((ks * 2 + b_h) ^ (n & 7));
                LDM_X4(Bf[2 * np][0], Bf[2 * np][1], Bf[2 * np + 1][0], Bf[2 * np + 1][1],
                       sB + n * 128 + (c << 4));
            }
            #pragma unroll
            for (int mt = 0; mt < 2; mt++)
                #pragma unroll
                for (int nt = 0; nt < 8; nt++)
                    MMA16816(acc[mt][nt], Ah[mt], Bf[nt]);
        }
    }

    // ---- epilogue: bias + YOLO decode -> stage smem -> one bulk store ----
    __syncthreads();   // done with GEMM smem; reuse as stage
    const float* bs = (const float*)(smem + S_BIAS);
    const int g  = lid >> 2;
    const int t4 = lid & 3;

    #pragma unroll
    for (int mt = 0; mt < 2; mt++) {
        #pragma unroll
        for (int e = 0; e < 2; e++) {
            const int row = wm * 32 + mt * 16 + g + e * 8;
            const int gmr = m0 + row;
            const int bi  = gmr / HW;
            const int hw  = gmr - bi * HW;
            const int hh  = hw / 38;
            const int wwp = hw - hh * 38;
            float* srow = (float*)(smem + S_STAGE) + row * NOUT;
            #pragma unroll
            for (int nt = 0; nt < 8; nt++) {
                #pragma unroll
                for (int q = 0; q < 2; q++) {
                    const int o = wn * 64 + nt * 8 + t4 * 2 + q;
                    if (o >= NOUT) continue;
                    float v = acc[mt][nt][e * 2 + q] + bs[o];
                    const int ai = (o >= 170) ? 2 : ((o >= 85) ? 1 : 0);
                    const int c  = o - ai * 85;
                    if (c == 0)      v = (1.0f / (1.0f + __expf(-v)) + (float)wwp) * 16.0f;
                    else if (c == 1) v = (1.0f / (1.0f + __expf(-v)) + (float)hh) * 16.0f;
                    else if (c == 2) v = __expf(v) * c_anch[ai][0];
                    else if (c == 3) v = __expf(v) * c_anch[ai][1];
                    srow[o] = v;
                }
            }
        }
    }
    __syncthreads();

    if (tid == 0) {
        asm volatile("fence.proxy.async;" ::: "memory");
        float* gdst = out + (size_t)m0 * NOUT;
        asm volatile("cp.async.bulk.global.shared::cta.bulk_group [%0], [%1], %2;"
                     :: "l"(gdst), "r"(sb + S_STAGE), "r"((uint32_t)(BM * NOUT * 4)) : "memory");
        asm volatile("cp.async.bulk.commit_group;" ::: "memory");
        asm volatile("cp.async.bulk.wait_group 0;" ::: "memory");
    }
}

extern "C" void kernel_launch(void* const* d_in, const int* in_sizes, int n_in,
                              void* d_out, int out_size)
{
    const float* xin    = (const float*)d_in[0];   // [32, 512, 38, 38]
    const float* conv_w = (const float*)d_in[1];   // [255, 512]
    const float* conv_b = (const float*)d_in[2];   // [255]
    float* out = (float*)d_out;                    // [32, 38, 38, 3, 85]

    cudaFuncSetAttribute(yolo_mma_kernel,
                         cudaFuncAttributeMaxDynamicSharedMemorySize, S_TOTAL);

    prep_w<<<512, 256>>>(conv_w);
    yolo_mma_kernel<<<NTILES, THREADS, S_TOTAL>>>(xin, conv_b, out);
}